// round 16
// baseline (speedup 1.0000x reference)
#include <cuda_runtime.h>
#include <cuda_fp16.h>
#include <math.h>
#include <stdint.h>

#define BB   64
#define NN   8
#define FF   4096
#define H1   1024
#define H2   1024
#define OUTC 512
#define S    (BB*FF)
#define NK   1025
#define MAXEV 26000
#define NSEG 16
#define SEGL 64
#define CH   4

__device__ float    g_m[S];
__device__ float    g_s0[H1];
__device__ float    g_bk[H1];
__device__ int      g_bu[H1];
__device__ float    g_alpha[NK*H2];
__device__ float    g_beta [NK*H2];
__device__ float    g_W2T[H2*OUTC];
__device__ int      g_cnt[NK];
__device__ int      g_rank[NK];
__device__ int      g_base[NK];
__device__ int      g_nev;
__device__ unsigned g_mlo_u, g_mhi_u;
__device__ float    g_evm[MAXEV];
__device__ int      g_evp[MAXEV];
__device__ __half2  g_Th[(size_t)MAXEV*OUTC];   // (A2, C2) as half2
__device__ float    g_pa[NSEG*H2], g_pb[NSEG*H2];
__device__ float    g_ia[NSEG*H2], g_ib[NSEG*H2];
__device__ float    g_sa[NSEG*H2], g_sb[NSEG*H2];

__device__ __forceinline__ unsigned f2u(float f){
    unsigned u = __float_as_uint(f);
    return (u & 0x80000000u) ? ~u : (u | 0x80000000u);
}
__device__ __forceinline__ float u2f(unsigned e){
    return __uint_as_float((e & 0x80000000u) ? (e & 0x7FFFFFFFu) : ~e);
}
__device__ __forceinline__ unsigned long long pk2(float a, float b){
    unsigned long long r;
    asm("mov.b64 %0, {%1, %2};" : "=l"(r) : "r"(__float_as_uint(a)), "r"(__float_as_uint(b)));
    return r;
}
__device__ __forceinline__ float2 upk2(unsigned long long v){
    unsigned a, b;
    asm("mov.b64 {%0, %1}, %2;" : "=r"(a), "=r"(b) : "l"(v));
    return make_float2(__uint_as_float(a), __uint_as_float(b));
}
__device__ __forceinline__ unsigned long long ffma2(unsigned long long a,
                                                    unsigned long long b,
                                                    unsigned long long c){
    unsigned long long d;
    asm("fma.rn.f32x2 %0, %1, %2, %3;" : "=l"(d) : "l"(a), "l"(b), "l"(c));
    return d;
}

// fused: init counters + prep breakpoints + bitonic sort (one block)
__global__ void __launch_bounds__(1024) k_setup(const float* __restrict__ W0,
                                                const float* __restrict__ b0){
    __shared__ float sk[1024];
    __shared__ int   sv[1024];
    int t = threadIdx.x;
    g_cnt[t] = 0; g_rank[t] = 0;
    if (t == 0){
        g_cnt[1024] = 0; g_rank[1024] = 0;
        g_mlo_u = 0xFFFFFFFFu; g_mhi_u = 0u;
    }
    float s = 0.f;
    #pragma unroll
    for (int c = 0; c < NN; c++) s += W0[t*NN + c];
    g_s0[t] = s;
    float tt;
    if (s != 0.f){
        tt = -b0[t] / s;
        if (!isfinite(tt)) tt = (tt > 0.f) ? 3e37f : -3e37f;
    } else tt = 3e37f;
    sk[t] = tt; sv[t] = t;
    __syncthreads();
    for (int size = 2; size <= 1024; size <<= 1){
        for (int stride = size >> 1; stride > 0; stride >>= 1){
            int i = t, j = i ^ stride;
            if (j > i){
                bool up = ((i & size) == 0);
                float ki = sk[i], kj = sk[j];
                int   vi = sv[i], vj = sv[j];
                bool gt = (ki > kj) || (ki == kj && vi > vj);
                if (gt == up){ sk[i]=kj; sk[j]=ki; sv[i]=vj; sv[j]=vi; }
            }
            __syncthreads();
        }
    }
    g_bk[t] = sk[t]; g_bu[t] = sv[t];
}

__global__ void k_mean(const float* __restrict__ x){
    int s = blockIdx.x*256 + threadIdx.x;
    int b = s >> 12, f = s & 4095;
    const float* xp = x + ((size_t)b*NN)*FF + f;
    float sum = 0.f;
    #pragma unroll
    for (int n = 0; n < NN; n++) sum += xp[(size_t)n*FF];
    float m = sum * (1.0f/NN);
    g_m[s] = m;
    unsigned e = f2u(m);
    __shared__ unsigned smin[256], smax[256];
    int t = threadIdx.x;
    smin[t] = e; smax[t] = e; __syncthreads();
    for (int st = 128; st > 0; st >>= 1){
        if (t < st){
            smin[t] = min(smin[t], smin[t+st]);
            smax[t] = max(smax[t], smax[t+st]);
        }
        __syncthreads();
    }
    if (t == 0){ atomicMin(&g_mlo_u, smin[0]); atomicMax(&g_mhi_u, smax[0]); }
}

__global__ void k_tr(const float* __restrict__ W2){
    int idx = blockIdx.x*512 + threadIdx.x;
    int o = idx >> 9, j = idx & 511;
    g_W2T[idx] = W2[(size_t)j*H2 + o];
}

__global__ void __launch_bounds__(128) k_sweepA(const float* __restrict__ W1,
                                                const float* __restrict__ b0_in){
    int s = blockIdx.x;
    int o = blockIdx.y*128 + threadIdx.x;
    __shared__ int   s_u[SEGL];
    __shared__ float s_s0[SEGL];
    __shared__ float s_b0[SEGL];
    if (threadIdx.x < SEGL){
        int kk = s*SEGL + threadIdx.x;
        int u = g_bu[kk];
        s_u[threadIdx.x] = u;
        s_s0[threadIdx.x] = g_s0[u];
        s_b0[threadIdx.x] = b0_in[u];
    }
    __syncthreads();
    const float* W1row = W1 + (size_t)o*H1;
    float da = 0.f, db = 0.f, ia = 0.f, ib = 0.f;
    #pragma unroll 8
    for (int i = 0; i < SEGL; i++){
        float s0v = s_s0[i], b0v = s_b0[i];
        float w = W1row[s_u[i]];
        float sgn = (s0v > 0.f) ? 1.f : ((s0v < 0.f) ? -1.f : 0.f);
        da = fmaf(sgn*w, s0v, da);
        db = fmaf(sgn*w, b0v, db);
        bool act0 = (s0v < 0.f) || (s0v == 0.f && b0v > 0.f);
        if (act0){
            ia = fmaf(w, s0v, ia);
            ib = fmaf(w, b0v, ib);
        }
    }
    g_pa[s*H2 + o] = da; g_pb[s*H2 + o] = db;
    g_ia[s*H2 + o] = ia; g_ib[s*H2 + o] = ib;
}

// per-o scan across segments + tail row + tail-interval crossing count
__global__ void __launch_bounds__(128) k_sweepB(const float* __restrict__ b1){
    int o = blockIdx.x*128 + threadIdx.x;
    float ia = 0.f, ib = 0.f;
    #pragma unroll
    for (int s = 0; s < NSEG; s++){ ia += g_ia[s*H2 + o]; ib += g_ib[s*H2 + o]; }
    ib += b1[o];
    float a = ia, bt = ib;
    #pragma unroll
    for (int s = 0; s < NSEG; s++){
        g_sa[s*H2 + o] = a; g_sb[s*H2 + o] = bt;
        a  += g_pa[s*H2 + o];
        bt += g_pb[s*H2 + o];
    }
    g_alpha[1024*H2 + o] = a;
    g_beta [1024*H2 + o] = bt;
    float mlo = u2f(g_mlo_u), mhi = u2f(g_mhi_u);
    float L = fmaxf(g_bk[1023], mlo), R = mhi;
    if (L < R){
        bool sL = fmaf(a, L, bt) > 0.f;
        bool sR = fmaf(a, R, bt) > 0.f;
        if (sL != sR) atomicAdd(&g_cnt[1024], 1);
    }
}

// materialize alpha/beta rows + fused per-interval crossing count
__global__ void __launch_bounds__(128) k_sweepC(const float* __restrict__ W1,
                                                const float* __restrict__ b0_in){
    int s = blockIdx.x;
    int o = blockIdx.y*128 + threadIdx.x;
    __shared__ int   s_u[SEGL];
    __shared__ float s_s0[SEGL];
    __shared__ float s_b0[SEGL];
    __shared__ float s_bkL[SEGL];
    __shared__ float s_bkR[SEGL];
    if (threadIdx.x < SEGL){
        int kk = s*SEGL + threadIdx.x;
        int u = g_bu[kk];
        s_u[threadIdx.x] = u;
        s_s0[threadIdx.x] = g_s0[u];
        s_b0[threadIdx.x] = b0_in[u];
        s_bkL[threadIdx.x] = (kk == 0) ? -3e38f : g_bk[kk-1];
        s_bkR[threadIdx.x] = g_bk[kk];
    }
    __syncthreads();
    float mlo = u2f(g_mlo_u), mhi = u2f(g_mhi_u);
    const float* W1row = W1 + (size_t)o*H1;
    float a = g_sa[s*H2 + o], bt = g_sb[s*H2 + o];
    #pragma unroll 8
    for (int i = 0; i < SEGL; i++){
        int kk = s*SEGL + i;
        g_alpha[kk*H2 + o] = a;
        g_beta [kk*H2 + o] = bt;
        float L = fmaxf(s_bkL[i], mlo), R = fminf(s_bkR[i], mhi);
        if (L < R){
            bool sL = fmaf(a, L, bt) > 0.f;
            bool sR = fmaf(a, R, bt) > 0.f;
            if (sL != sR) atomicAdd(&g_cnt[kk], 1);
        }
        float s0v = s_s0[i];
        float w = W1row[s_u[i]];
        float sgn = (s0v > 0.f) ? 1.f : ((s0v < 0.f) ? -1.f : 0.f);
        a  = fmaf(sgn*w, s0v,     a);
        bt = fmaf(sgn*w, s_b0[i], bt);
    }
}

__global__ void k_scan(){
    __shared__ int sv[1024];
    int t = threadIdx.x;
    float mlo = u2f(g_mlo_u), mhi = u2f(g_mhi_u);
    int bnd = (g_bk[t] > mlo && g_bk[t] < mhi) ? 1 : 0;
    int v = g_cnt[t] + bnd;
    sv[t] = v; __syncthreads();
    for (int off = 1; off < 1024; off <<= 1){
        int x = (t >= off) ? sv[t-off] : 0;
        __syncthreads();
        sv[t] += x;
        __syncthreads();
    }
    g_base[t] = sv[t] - v;
    if (t == 1023){
        g_base[1024] = sv[1023];
        int acc = sv[1023] + g_cnt[1024];
        if (acc > MAXEV) acc = MAXEV;
        g_nev = acc;
    }
}

__global__ void k_fill(){
    int k = blockIdx.x;
    int o = blockIdx.y*256 + threadIdx.x;
    float mlo = u2f(g_mlo_u), mhi = u2f(g_mhi_u);
    if (blockIdx.y == 0 && threadIdx.x == 0 && k < 1024){
        float t = g_bk[k];
        if (t > mlo && t < mhi){
            int pos = g_base[k] + g_cnt[k];
            if (pos < MAXEV){ g_evm[pos] = t; g_evp[pos] = (1 << 21); }
        }
    }
    float tL = (k == 0)    ? -3e38f : g_bk[k-1];
    float tR = (k == 1024) ?  3e38f : g_bk[k];
    float L = fmaxf(tL, mlo), R = fminf(tR, mhi);
    if (!(L < R)) return;
    float a = g_alpha[k*H2 + o], b = g_beta[k*H2 + o];
    bool sL = fmaf(a, L, b) > 0.f;
    bool sR = fmaf(a, R, b) > 0.f;
    if (sL != sR){
        float ms = -b / a;
        ms = fminf(fmaxf(ms, L), R);
        int rk = atomicAdd(&g_rank[k], 1);
        int pos = g_base[k] + rk;
        if (pos < MAXEV){
            g_evm[pos] = ms;
            g_evp[pos] = o | (sR ? (1 << 20) : 0);
        }
    }
}

__global__ void k_segsort(){
    int k = blockIdx.x*256 + threadIdx.x;
    if (k >= NK) return;
    int s = g_base[k], n = g_cnt[k];
    if (s + n > MAXEV) n = MAXEV - s;
    for (int i = 1; i < n; i++){
        float key = g_evm[s+i]; int p = g_evp[s+i];
        int j = i - 1;
        while (j >= 0 && (g_evm[s+j] > key || (g_evm[s+j] == key && g_evp[s+j] > p))){
            g_evm[s+j+1] = g_evm[s+j]; g_evp[s+j+1] = g_evp[s+j]; j--;
        }
        g_evm[s+j+1] = key; g_evp[s+j+1] = p;
    }
}

// CH=4 intervals per block; [o][pair] vectorized gated table,
// f32x2 accumulate, half2 store (R13 chain).
__global__ void __launch_bounds__(512) k_chain(const float* __restrict__ b2){
    int k0 = blockIdx.x*CH;
    float mlo = u2f(g_mlo_u), mhi = u2f(g_mhi_u);

    __shared__ ulonglong2 s_gp[1024][2];

    bool any = false;
    bool act[CH]; float midc[CH];
    #pragma unroll
    for (int c = 0; c < CH; c++){
        int k = k0 + c;
        act[c] = false; midc[c] = 0.f;
        if (k < NK){
            float tL = (k == 0)    ? -3e38f : g_bk[k-1];
            float tR = (k == 1024) ?  3e38f : g_bk[k];
            float L = fmaxf(tL, mlo), R = fminf(tR, mhi);
            if (L < R){
                int r0 = g_base[k]; int ne = g_cnt[k];
                float right = (ne > 0 && r0 < MAXEV) ? g_evm[r0] : R;
                midc[c] = 0.5f*(L + right);
                act[c] = true; any = true;
            }
        }
    }
    if (!any) return;

    for (int o = threadIdx.x; o < 1024; o += 512){
        unsigned long long v[CH];
        #pragma unroll
        for (int c = 0; c < CH; c++){
            v[c] = 0ull;
            if (act[c]){
                int k = k0 + c;
                float av = g_alpha[k*H2 + o];
                float bv = g_beta [k*H2 + o];
                if (fmaf(av, midc[c], bv) > 0.f) v[c] = pk2(av, bv);
            }
        }
        s_gp[o][0] = make_ulonglong2(v[0], v[1]);
        s_gp[o][1] = make_ulonglong2(v[2], v[3]);
    }
    __syncthreads();

    int j = threadIdx.x;
    float bb = b2[j];
    unsigned long long acc0 = pk2(0.f, bb);
    unsigned long long acc1 = acc0, acc2 = acc0, acc3 = acc0;

    #pragma unroll 4
    for (int o = 0; o < 1024; o++){
        float w = g_W2T[o*OUTC + j];
        unsigned long long wp = pk2(w, w);
        ulonglong2 p0 = s_gp[o][0];
        ulonglong2 p1 = s_gp[o][1];
        acc0 = ffma2(p0.x, wp, acc0);
        acc1 = ffma2(p0.y, wp, acc1);
        acc2 = ffma2(p1.x, wp, acc2);
        acc3 = ffma2(p1.y, wp, acc3);
    }

    unsigned long long accs[CH] = {acc0, acc1, acc2, acc3};
    #pragma unroll
    for (int c = 0; c < CH; c++){
        if (!act[c]) continue;
        int k = k0 + c;
        int r0 = g_base[k], ne = g_cnt[k];
        if (r0 >= MAXEV) continue;
        if (r0 + ne >= MAXEV) ne = MAXEV - 1 - r0;
        float2 ac = upk2(accs[c]);
        float a = ac.x, cc = ac.y;
        g_Th[(size_t)r0*OUTC + j] = __floats2half2_rn(a, cc);
        for (int e = 0; e < ne; e++){
            int p = g_evp[r0 + e];
            int oo = p & 1023;
            float sgn = (p & (1 << 20)) ? 1.f : -1.f;
            float w  = g_W2T[oo*OUTC + j];
            float av = g_alpha[k*H2 + oo];
            float bv = g_beta [k*H2 + oo];
            a  = fmaf(sgn*av, w, a);
            cc = fmaf(sgn*bv, w, cc);
            g_Th[(size_t)(r0+1+e)*OUTC + j] = __floats2half2_rn(a, cc);
        }
    }
}

// staged apply; output stores are STREAMING (__stcs) so the 537 MB write
// stream doesn't evict the 53 MB table from L2.
__global__ void __launch_bounds__(256) k_apply(float* __restrict__ out){
    __shared__ int      s_lo[64];
    __shared__ float    s_m[64];
    __shared__ unsigned sT[64][65];
    int t = threadIdx.x;
    int s0 = blockIdx.x * 64;
    if (t < 64){
        float m = g_m[s0 + t];
        int lo = 0, hi = g_nev;
        while (lo < hi){
            int mid = (lo + hi) >> 1;
            if (g_evm[mid] <= m) lo = mid + 1; else hi = mid;
        }
        s_lo[t] = lo; s_m[t] = m;
    }
    __syncthreads();
    int b  = s0 >> 12;
    int f0 = s0 & 4095;
    int sg4 = (t & 15) * 4;
    int cg  = t >> 4;
    float4 m4;
    m4.x = s_m[sg4+0]; m4.y = s_m[sg4+1]; m4.z = s_m[sg4+2]; m4.w = s_m[sg4+3];
    float* obase = out + (size_t)b*OUTC*FF + f0 + sg4;

    for (int cc = 0; cc < 8; cc++){
        int c0 = cc * 64;
        #pragma unroll
        for (int i = 0; i < 4; i++){
            int e = t + 256*i;
            int si = e >> 4;
            int q  = e & 15;
            const uint4* pT = (const uint4*)(g_Th + (size_t)s_lo[si]*OUTC + c0) + q;
            uint4 v = __ldg(pT);
            sT[si][q*4+0] = v.x; sT[si][q*4+1] = v.y;
            sT[si][q*4+2] = v.z; sT[si][q*4+3] = v.w;
        }
        __syncthreads();
        #pragma unroll
        for (int r = 0; r < 4; r++){
            int ch = cg*4 + r;
            int o  = c0 + ch;
            unsigned u0 = sT[sg4+0][ch];
            unsigned u1 = sT[sg4+1][ch];
            unsigned u2 = sT[sg4+2][ch];
            unsigned u3 = sT[sg4+3][ch];
            float2 t0 = __half22float2(*reinterpret_cast<__half2*>(&u0));
            float2 t1 = __half22float2(*reinterpret_cast<__half2*>(&u1));
            float2 t2 = __half22float2(*reinterpret_cast<__half2*>(&u2));
            float2 t3 = __half22float2(*reinterpret_cast<__half2*>(&u3));
            float4 res;
            res.x = fmaf(m4.x, t0.x, t0.y);
            res.y = fmaf(m4.y, t1.x, t1.y);
            res.z = fmaf(m4.z, t2.x, t2.y);
            res.w = fmaf(m4.w, t3.x, t3.y);
            __stcs((float4*)(obase + (size_t)o*FF), res);
        }
        __syncthreads();
    }
}

extern "C" void kernel_launch(void* const* d_in, const int* in_sizes, int n_in,
                              void* d_out, int out_size){
    const float* x  = (const float*)d_in[0];
    const float* W0 = (const float*)d_in[1];
    const float* b0 = (const float*)d_in[2];
    const float* W1 = (const float*)d_in[3];
    const float* b1 = (const float*)d_in[4];
    const float* W2 = (const float*)d_in[5];
    const float* b2 = (const float*)d_in[6];
    float* out = (float*)d_out;

    k_setup  <<<1, 1024>>>(W0, b0);
    k_mean   <<<S/256, 256>>>(x);
    k_tr     <<<H2*OUTC/512, 512>>>(W2);
    k_sweepA <<<dim3(NSEG, H2/128), 128>>>(W1, b0);
    k_sweepB <<<H2/128, 128>>>(b1);
    k_sweepC <<<dim3(NSEG, H2/128), 128>>>(W1, b0);
    k_scan   <<<1, 1024>>>();
    k_fill   <<<dim3(NK, 4), 256>>>();
    k_segsort<<<(NK+255)/256, 256>>>();
    k_chain  <<<(NK+CH-1)/CH, 512>>>(b2);
    k_apply  <<<S/64, 256>>>(out);
}

// round 17
// speedup vs baseline: 1.4822x; 1.4822x over previous
#include <cuda_runtime.h>
#include <cuda_fp16.h>
#include <math.h>
#include <stdint.h>

#define BB   64
#define NN   8
#define FF   4096
#define H1   1024
#define H2   1024
#define OUTC 512
#define S    (BB*FF)
#define NK   1025
#define MAXEV 26000
#define NSEG 16
#define SEGL 64
#define CH   4

__device__ float    g_m[S];
__device__ float    g_s0[H1];
__device__ float    g_bk[H1];
__device__ int      g_bu[H1];
__device__ float    g_alpha[NK*H2];
__device__ float    g_beta [NK*H2];
__device__ float    g_W2T[H2*OUTC];
__device__ int      g_cnt[NK];
__device__ int      g_rank[NK];
__device__ int      g_base[NK];
__device__ int      g_nev;
__device__ unsigned g_mlo_u, g_mhi_u;
__device__ float    g_evm[MAXEV];
__device__ int      g_evp[MAXEV];
__device__ __half2  g_Th[(size_t)MAXEV*OUTC];   // (A2, C2) as half2
__device__ float    g_pa[NSEG*H2], g_pb[NSEG*H2];
__device__ float    g_ia[NSEG*H2], g_ib[NSEG*H2];
__device__ float    g_sa[NSEG*H2], g_sb[NSEG*H2];

__device__ __forceinline__ unsigned f2u(float f){
    unsigned u = __float_as_uint(f);
    return (u & 0x80000000u) ? ~u : (u | 0x80000000u);
}
__device__ __forceinline__ float u2f(unsigned e){
    return __uint_as_float((e & 0x80000000u) ? (e & 0x7FFFFFFFu) : ~e);
}
__device__ __forceinline__ unsigned long long pk2(float a, float b){
    unsigned long long r;
    asm("mov.b64 %0, {%1, %2};" : "=l"(r) : "r"(__float_as_uint(a)), "r"(__float_as_uint(b)));
    return r;
}
__device__ __forceinline__ float2 upk2(unsigned long long v){
    unsigned a, b;
    asm("mov.b64 {%0, %1}, %2;" : "=r"(a), "=r"(b) : "l"(v));
    return make_float2(__uint_as_float(a), __uint_as_float(b));
}
__device__ __forceinline__ unsigned long long ffma2(unsigned long long a,
                                                    unsigned long long b,
                                                    unsigned long long c){
    unsigned long long d;
    asm("fma.rn.f32x2 %0, %1, %2, %3;" : "=l"(d) : "l"(a), "l"(b), "l"(c));
    return d;
}

// fused: init counters + prep breakpoints + bitonic sort (one block)
__global__ void __launch_bounds__(1024) k_setup(const float* __restrict__ W0,
                                                const float* __restrict__ b0){
    __shared__ float sk[1024];
    __shared__ int   sv[1024];
    int t = threadIdx.x;
    g_cnt[t] = 0; g_rank[t] = 0;
    if (t == 0){
        g_cnt[1024] = 0; g_rank[1024] = 0;
        g_mlo_u = 0xFFFFFFFFu; g_mhi_u = 0u;
    }
    float s = 0.f;
    #pragma unroll
    for (int c = 0; c < NN; c++) s += W0[t*NN + c];
    g_s0[t] = s;
    float tt;
    if (s != 0.f){
        tt = -b0[t] / s;
        if (!isfinite(tt)) tt = (tt > 0.f) ? 3e37f : -3e37f;
    } else tt = 3e37f;
    sk[t] = tt; sv[t] = t;
    __syncthreads();
    for (int size = 2; size <= 1024; size <<= 1){
        for (int stride = size >> 1; stride > 0; stride >>= 1){
            int i = t, j = i ^ stride;
            if (j > i){
                bool up = ((i & size) == 0);
                float ki = sk[i], kj = sk[j];
                int   vi = sv[i], vj = sv[j];
                bool gt = (ki > kj) || (ki == kj && vi > vj);
                if (gt == up){ sk[i]=kj; sk[j]=ki; sv[i]=vj; sv[j]=vi; }
            }
            __syncthreads();
        }
    }
    g_bk[t] = sk[t]; g_bu[t] = sv[t];
}

__global__ void k_mean(const float* __restrict__ x){
    int s = blockIdx.x*256 + threadIdx.x;
    int b = s >> 12, f = s & 4095;
    const float* xp = x + ((size_t)b*NN)*FF + f;
    float sum = 0.f;
    #pragma unroll
    for (int n = 0; n < NN; n++) sum += xp[(size_t)n*FF];
    float m = sum * (1.0f/NN);
    g_m[s] = m;
    unsigned e = f2u(m);
    __shared__ unsigned smin[256], smax[256];
    int t = threadIdx.x;
    smin[t] = e; smax[t] = e; __syncthreads();
    for (int st = 128; st > 0; st >>= 1){
        if (t < st){
            smin[t] = min(smin[t], smin[t+st]);
            smax[t] = max(smax[t], smax[t+st]);
        }
        __syncthreads();
    }
    if (t == 0){ atomicMin(&g_mlo_u, smin[0]); atomicMax(&g_mhi_u, smax[0]); }
}

__global__ void k_tr(const float* __restrict__ W2){
    int idx = blockIdx.x*512 + threadIdx.x;
    int o = idx >> 9, j = idx & 511;
    g_W2T[idx] = W2[(size_t)j*H2 + o];
}

__global__ void __launch_bounds__(128) k_sweepA(const float* __restrict__ W1,
                                                const float* __restrict__ b0_in){
    int s = blockIdx.x;
    int o = blockIdx.y*128 + threadIdx.x;
    __shared__ int   s_u[SEGL];
    __shared__ float s_s0[SEGL];
    __shared__ float s_b0[SEGL];
    if (threadIdx.x < SEGL){
        int kk = s*SEGL + threadIdx.x;
        int u = g_bu[kk];
        s_u[threadIdx.x] = u;
        s_s0[threadIdx.x] = g_s0[u];
        s_b0[threadIdx.x] = b0_in[u];
    }
    __syncthreads();
    const float* W1row = W1 + (size_t)o*H1;
    float da = 0.f, db = 0.f, ia = 0.f, ib = 0.f;
    #pragma unroll 8
    for (int i = 0; i < SEGL; i++){
        float s0v = s_s0[i], b0v = s_b0[i];
        float w = W1row[s_u[i]];
        float sgn = (s0v > 0.f) ? 1.f : ((s0v < 0.f) ? -1.f : 0.f);
        da = fmaf(sgn*w, s0v, da);
        db = fmaf(sgn*w, b0v, db);
        bool act0 = (s0v < 0.f) || (s0v == 0.f && b0v > 0.f);
        if (act0){
            ia = fmaf(w, s0v, ia);
            ib = fmaf(w, b0v, ib);
        }
    }
    g_pa[s*H2 + o] = da; g_pb[s*H2 + o] = db;
    g_ia[s*H2 + o] = ia; g_ib[s*H2 + o] = ib;
}

// per-o scan across segments + tail row + tail-interval crossing count
__global__ void __launch_bounds__(128) k_sweepB(const float* __restrict__ b1){
    int o = blockIdx.x*128 + threadIdx.x;
    float ia = 0.f, ib = 0.f;
    #pragma unroll
    for (int s = 0; s < NSEG; s++){ ia += g_ia[s*H2 + o]; ib += g_ib[s*H2 + o]; }
    ib += b1[o];
    float a = ia, bt = ib;
    #pragma unroll
    for (int s = 0; s < NSEG; s++){
        g_sa[s*H2 + o] = a; g_sb[s*H2 + o] = bt;
        a  += g_pa[s*H2 + o];
        bt += g_pb[s*H2 + o];
    }
    g_alpha[1024*H2 + o] = a;
    g_beta [1024*H2 + o] = bt;
    float mlo = u2f(g_mlo_u), mhi = u2f(g_mhi_u);
    float L = fmaxf(g_bk[1023], mlo), R = mhi;
    if (L < R){
        bool sL = fmaf(a, L, bt) > 0.f;
        bool sR = fmaf(a, R, bt) > 0.f;
        if (sL != sR) atomicAdd(&g_cnt[1024], 1);
    }
}

// materialize alpha/beta rows + fused per-interval crossing count
__global__ void __launch_bounds__(128) k_sweepC(const float* __restrict__ W1,
                                                const float* __restrict__ b0_in){
    int s = blockIdx.x;
    int o = blockIdx.y*128 + threadIdx.x;
    __shared__ int   s_u[SEGL];
    __shared__ float s_s0[SEGL];
    __shared__ float s_b0[SEGL];
    __shared__ float s_bkL[SEGL];
    __shared__ float s_bkR[SEGL];
    if (threadIdx.x < SEGL){
        int kk = s*SEGL + threadIdx.x;
        int u = g_bu[kk];
        s_u[threadIdx.x] = u;
        s_s0[threadIdx.x] = g_s0[u];
        s_b0[threadIdx.x] = b0_in[u];
        s_bkL[threadIdx.x] = (kk == 0) ? -3e38f : g_bk[kk-1];
        s_bkR[threadIdx.x] = g_bk[kk];
    }
    __syncthreads();
    float mlo = u2f(g_mlo_u), mhi = u2f(g_mhi_u);
    const float* W1row = W1 + (size_t)o*H1;
    float a = g_sa[s*H2 + o], bt = g_sb[s*H2 + o];
    #pragma unroll 8
    for (int i = 0; i < SEGL; i++){
        int kk = s*SEGL + i;
        g_alpha[kk*H2 + o] = a;
        g_beta [kk*H2 + o] = bt;
        float L = fmaxf(s_bkL[i], mlo), R = fminf(s_bkR[i], mhi);
        if (L < R){
            bool sL = fmaf(a, L, bt) > 0.f;
            bool sR = fmaf(a, R, bt) > 0.f;
            if (sL != sR) atomicAdd(&g_cnt[kk], 1);
        }
        float s0v = s_s0[i];
        float w = W1row[s_u[i]];
        float sgn = (s0v > 0.f) ? 1.f : ((s0v < 0.f) ? -1.f : 0.f);
        a  = fmaf(sgn*w, s0v,     a);
        bt = fmaf(sgn*w, s_b0[i], bt);
    }
}

__global__ void k_scan(){
    __shared__ int sv[1024];
    int t = threadIdx.x;
    float mlo = u2f(g_mlo_u), mhi = u2f(g_mhi_u);
    int bnd = (g_bk[t] > mlo && g_bk[t] < mhi) ? 1 : 0;
    int v = g_cnt[t] + bnd;
    sv[t] = v; __syncthreads();
    for (int off = 1; off < 1024; off <<= 1){
        int x = (t >= off) ? sv[t-off] : 0;
        __syncthreads();
        sv[t] += x;
        __syncthreads();
    }
    g_base[t] = sv[t] - v;
    if (t == 1023){
        g_base[1024] = sv[1023];
        int acc = sv[1023] + g_cnt[1024];
        if (acc > MAXEV) acc = MAXEV;
        g_nev = acc;
    }
}

__global__ void k_fill(){
    int k = blockIdx.x;
    int o = blockIdx.y*256 + threadIdx.x;
    float mlo = u2f(g_mlo_u), mhi = u2f(g_mhi_u);
    if (blockIdx.y == 0 && threadIdx.x == 0 && k < 1024){
        float t = g_bk[k];
        if (t > mlo && t < mhi){
            int pos = g_base[k] + g_cnt[k];
            if (pos < MAXEV){ g_evm[pos] = t; g_evp[pos] = (1 << 21); }
        }
    }
    float tL = (k == 0)    ? -3e38f : g_bk[k-1];
    float tR = (k == 1024) ?  3e38f : g_bk[k];
    float L = fmaxf(tL, mlo), R = fminf(tR, mhi);
    if (!(L < R)) return;
    float a = g_alpha[k*H2 + o], b = g_beta[k*H2 + o];
    bool sL = fmaf(a, L, b) > 0.f;
    bool sR = fmaf(a, R, b) > 0.f;
    if (sL != sR){
        float ms = -b / a;
        ms = fminf(fmaxf(ms, L), R);
        int rk = atomicAdd(&g_rank[k], 1);
        int pos = g_base[k] + rk;
        if (pos < MAXEV){
            g_evm[pos] = ms;
            g_evp[pos] = o | (sR ? (1 << 20) : 0);
        }
    }
}

__global__ void k_segsort(){
    int k = blockIdx.x*256 + threadIdx.x;
    if (k >= NK) return;
    int s = g_base[k], n = g_cnt[k];
    if (s + n > MAXEV) n = MAXEV - s;
    for (int i = 1; i < n; i++){
        float key = g_evm[s+i]; int p = g_evp[s+i];
        int j = i - 1;
        while (j >= 0 && (g_evm[s+j] > key || (g_evm[s+j] == key && g_evp[s+j] > p))){
            g_evm[s+j+1] = g_evm[s+j]; g_evp[s+j+1] = g_evp[s+j]; j--;
        }
        g_evm[s+j+1] = key; g_evp[s+j+1] = p;
    }
}

// CH=4 intervals per block; [o][pair] vectorized gated table,
// f32x2 accumulate, half2 store; W2T via __ldg.
__global__ void __launch_bounds__(512) k_chain(const float* __restrict__ b2){
    int k0 = blockIdx.x*CH;
    float mlo = u2f(g_mlo_u), mhi = u2f(g_mhi_u);

    __shared__ ulonglong2 s_gp[1024][2];

    bool any = false;
    bool act[CH]; float midc[CH];
    #pragma unroll
    for (int c = 0; c < CH; c++){
        int k = k0 + c;
        act[c] = false; midc[c] = 0.f;
        if (k < NK){
            float tL = (k == 0)    ? -3e38f : g_bk[k-1];
            float tR = (k == 1024) ?  3e38f : g_bk[k];
            float L = fmaxf(tL, mlo), R = fminf(tR, mhi);
            if (L < R){
                int r0 = g_base[k]; int ne = g_cnt[k];
                float right = (ne > 0 && r0 < MAXEV) ? g_evm[r0] : R;
                midc[c] = 0.5f*(L + right);
                act[c] = true; any = true;
            }
        }
    }
    if (!any) return;

    for (int o = threadIdx.x; o < 1024; o += 512){
        unsigned long long v[CH];
        #pragma unroll
        for (int c = 0; c < CH; c++){
            v[c] = 0ull;
            if (act[c]){
                int k = k0 + c;
                float av = g_alpha[k*H2 + o];
                float bv = g_beta [k*H2 + o];
                if (fmaf(av, midc[c], bv) > 0.f) v[c] = pk2(av, bv);
            }
        }
        s_gp[o][0] = make_ulonglong2(v[0], v[1]);
        s_gp[o][1] = make_ulonglong2(v[2], v[3]);
    }
    __syncthreads();

    int j = threadIdx.x;
    float bb = b2[j];
    unsigned long long acc0 = pk2(0.f, bb);
    unsigned long long acc1 = acc0, acc2 = acc0, acc3 = acc0;

    #pragma unroll 4
    for (int o = 0; o < 1024; o++){
        float w = __ldg(g_W2T + o*OUTC + j);
        unsigned long long wp = pk2(w, w);
        ulonglong2 p0 = s_gp[o][0];
        ulonglong2 p1 = s_gp[o][1];
        acc0 = ffma2(p0.x, wp, acc0);
        acc1 = ffma2(p0.y, wp, acc1);
        acc2 = ffma2(p1.x, wp, acc2);
        acc3 = ffma2(p1.y, wp, acc3);
    }

    unsigned long long accs[CH] = {acc0, acc1, acc2, acc3};
    #pragma unroll
    for (int c = 0; c < CH; c++){
        if (!act[c]) continue;
        int k = k0 + c;
        int r0 = g_base[k], ne = g_cnt[k];
        if (r0 >= MAXEV) continue;
        if (r0 + ne >= MAXEV) ne = MAXEV - 1 - r0;
        float2 ac = upk2(accs[c]);
        float a = ac.x, cc = ac.y;
        g_Th[(size_t)r0*OUTC + j] = __floats2half2_rn(a, cc);
        for (int e = 0; e < ne; e++){
            int p = g_evp[r0 + e];
            int oo = p & 1023;
            float sgn = (p & (1 << 20)) ? 1.f : -1.f;
            float w  = __ldg(g_W2T + oo*OUTC + j);
            float av = g_alpha[k*H2 + oo];
            float bv = g_beta [k*H2 + oo];
            a  = fmaf(sgn*av, w, a);
            cc = fmaf(sgn*bv, w, cc);
            g_Th[(size_t)(r0+1+e)*OUTC + j] = __floats2half2_rn(a, cc);
        }
    }
}

// staged apply (R10/R15 winner: plain stores)
__global__ void __launch_bounds__(256) k_apply(float* __restrict__ out){
    __shared__ int      s_lo[64];
    __shared__ float    s_m[64];
    __shared__ unsigned sT[64][65];
    int t = threadIdx.x;
    int s0 = blockIdx.x * 64;
    if (t < 64){
        float m = g_m[s0 + t];
        int lo = 0, hi = g_nev;
        while (lo < hi){
            int mid = (lo + hi) >> 1;
            if (g_evm[mid] <= m) lo = mid + 1; else hi = mid;
        }
        s_lo[t] = lo; s_m[t] = m;
    }
    __syncthreads();
    int b  = s0 >> 12;
    int f0 = s0 & 4095;
    int sg4 = (t & 15) * 4;
    int cg  = t >> 4;
    float4 m4;
    m4.x = s_m[sg4+0]; m4.y = s_m[sg4+1]; m4.z = s_m[sg4+2]; m4.w = s_m[sg4+3];
    float* obase = out + (size_t)b*OUTC*FF + f0 + sg4;

    for (int cc = 0; cc < 8; cc++){
        int c0 = cc * 64;
        #pragma unroll
        for (int i = 0; i < 4; i++){
            int e = t + 256*i;
            int si = e >> 4;
            int q  = e & 15;
            const uint4* pT = (const uint4*)(g_Th + (size_t)s_lo[si]*OUTC + c0) + q;
            uint4 v = __ldg(pT);
            sT[si][q*4+0] = v.x; sT[si][q*4+1] = v.y;
            sT[si][q*4+2] = v.z; sT[si][q*4+3] = v.w;
        }
        __syncthreads();
        #pragma unroll
        for (int r = 0; r < 4; r++){
            int ch = cg*4 + r;
            int o  = c0 + ch;
            unsigned u0 = sT[sg4+0][ch];
            unsigned u1 = sT[sg4+1][ch];
            unsigned u2 = sT[sg4+2][ch];
            unsigned u3 = sT[sg4+3][ch];
            float2 t0 = __half22float2(*reinterpret_cast<__half2*>(&u0));
            float2 t1 = __half22float2(*reinterpret_cast<__half2*>(&u1));
            float2 t2 = __half22float2(*reinterpret_cast<__half2*>(&u2));
            float2 t3 = __half22float2(*reinterpret_cast<__half2*>(&u3));
            float4 res;
            res.x = fmaf(m4.x, t0.x, t0.y);
            res.y = fmaf(m4.y, t1.x, t1.y);
            res.z = fmaf(m4.z, t2.x, t2.y);
            res.w = fmaf(m4.w, t3.x, t3.y);
            *(float4*)(obase + (size_t)o*FF) = res;
        }
        __syncthreads();
    }
}

extern "C" void kernel_launch(void* const* d_in, const int* in_sizes, int n_in,
                              void* d_out, int out_size){
    const float* x  = (const float*)d_in[0];
    const float* W0 = (const float*)d_in[1];
    const float* b0 = (const float*)d_in[2];
    const float* W1 = (const float*)d_in[3];
    const float* b1 = (const float*)d_in[4];
    const float* W2 = (const float*)d_in[5];
    const float* b2 = (const float*)d_in[6];
    float* out = (float*)d_out;

    k_setup  <<<1, 1024>>>(W0, b0);
    k_mean   <<<S/256, 256>>>(x);
    k_tr     <<<H2*OUTC/512, 512>>>(W2);
    k_sweepA <<<dim3(NSEG, H2/128), 128>>>(W1, b0);
    k_sweepB <<<H2/128, 128>>>(b1);
    k_sweepC <<<dim3(NSEG, H2/128), 128>>>(W1, b0);
    k_scan   <<<1, 1024>>>();
    k_fill   <<<dim3(NK, 4), 256>>>();
    k_segsort<<<(NK+255)/256, 256>>>();
    k_chain  <<<(NK+CH-1)/CH, 512>>>(b2);
    k_apply  <<<S/64, 256>>>(out);
}